// round 7
// baseline (speedup 1.0000x reference)
#include <cuda_runtime.h>

// loss = dot(colsum(a), colsum(b)),  a,b: [16384, 512] fp32  (2*LAMBD = 1.0)
// One fused kernel, 256 CTAs x 512 thr, scalar coalesced LDG.32 streamed (.cs),
// EXPLICIT 32-deep load batching (16a+16b temps) to force bytes-in-flight,
// atomics -> last-block finalize + state reset.

#define ROWS  16384
#define COLS  512
#define NBLK  256
#define TPB   512
#define RPB   (ROWS / NBLK)   // 64 rows per block
#define BATCH 16              // rows per batched group; 2*BATCH loads in flight

__device__ float g_sa[COLS];          // zero-init at module load; re-zeroed each call
__device__ float g_sb[COLS];
__device__ unsigned int g_ticket;

__global__ __launch_bounds__(TPB) void fused_kernel(const float* __restrict__ a,
                                                    const float* __restrict__ b,
                                                    float* __restrict__ out) {
    const int c  = threadIdx.x;              // column 0..511 (coalesced across warp)
    const int r0 = blockIdx.x * RPB;

    const float* pa = a + (size_t)r0 * COLS + c;
    const float* pb = b + (size_t)r0 * COLS + c;

    float s0 = 0.f, s1 = 0.f, s2 = 0.f, s3 = 0.f;   // a accumulators
    float t0 = 0.f, t1 = 0.f, t2 = 0.f, t3 = 0.f;   // b accumulators

#pragma unroll
    for (int g = 0; g < RPB / BATCH; ++g) {  // 4 groups of 16 rows
        float ta[BATCH], tb[BATCH];
#pragma unroll
        for (int j = 0; j < BATCH; ++j)      // 32 LDGs issued before any use
            ta[j] = __ldcs(pa + (size_t)(g * BATCH + j) * COLS);
#pragma unroll
        for (int j = 0; j < BATCH; ++j)
            tb[j] = __ldcs(pb + (size_t)(g * BATCH + j) * COLS);

#pragma unroll
        for (int j = 0; j < BATCH; j += 4) {
            s0 += ta[j + 0]; s1 += ta[j + 1]; s2 += ta[j + 2]; s3 += ta[j + 3];
            t0 += tb[j + 0]; t1 += tb[j + 1]; t2 += tb[j + 2]; t3 += tb[j + 3];
        }
    }
    float sa = (s0 + s1) + (s2 + s3);
    float sb = (t0 + t1) + (t2 + t3);

    atomicAdd(&g_sa[c], sa);
    atomicAdd(&g_sb[c], sb);

    // ---- last-block-done ticket ----
    __threadfence();
    __shared__ bool is_last;
    if (c == 0) {
        unsigned int t = atomicAdd(&g_ticket, 1u);
        is_last = (t == (unsigned)(gridDim.x - 1));
    }
    __syncthreads();
    if (!is_last) return;

    __threadfence();                         // acquire side

    float va = __ldcg(&g_sa[c]);
    float vb = __ldcg(&g_sb[c]);
    g_sa[c] = 0.0f;                          // reset for next graph replay
    g_sb[c] = 0.0f;

    float v = va * vb;
    __shared__ float red[16];
#pragma unroll
    for (int o = 16; o > 0; o >>= 1)
        v += __shfl_xor_sync(0xffffffffu, v, o);
    if ((c & 31) == 0) red[c >> 5] = v;
    __syncthreads();
    if (c < 16) {
        float w = red[c];
#pragma unroll
        for (int o = 8; o > 0; o >>= 1)
            w += __shfl_xor_sync(0xffffu, w, o);
        if (c == 0) {
            out[0] = w;                      // 2 * LAMBD = 1.0
            g_ticket = 0u;
        }
    }
}

extern "C" void kernel_launch(void* const* d_in, const int* in_sizes, int n_in,
                              void* d_out, int out_size) {
    const float* a = (const float*)d_in[0];
    const float* b = (const float*)d_in[1];
    float* out = (float*)d_out;

    fused_kernel<<<NBLK, TPB>>>(a, b, out);
}

// round 8
// speedup vs baseline: 1.4167x; 1.4167x over previous
#include <cuda_runtime.h>

// loss = dot(colsum(a), colsum(b)),  a,b: [16384, 512] fp32  (2*LAMBD = 1.0)
// One fused kernel: 256 CTAs x 1024 thr (2x warps vs champion, same atomic count).
// Each half-block sums 32 rows/column with scalar coalesced streamed LDG.32;
// smem fold -> 512 atomics/block -> last-block finalize + state reset.

#define ROWS 16384
#define COLS 512
#define NBLK 256
#define TPB  1024
#define RPB  64              // rows per block
#define RPT  (RPB / 2)       // 32 rows per thread (compile-time)

__device__ float g_sa[COLS];          // zero-init at module load; re-zeroed each call
__device__ float g_sb[COLS];
__device__ unsigned int g_ticket;

__global__ __launch_bounds__(TPB) void fused_kernel(const float* __restrict__ a,
                                                    const float* __restrict__ b,
                                                    float* __restrict__ out) {
    const int t    = threadIdx.x;
    const int c    = t & (COLS - 1);         // column 0..511 (coalesced)
    const int half = t >> 9;                 // 0 or 1
    const int r0   = blockIdx.x * RPB + half * RPT;

    const float* pa = a + (size_t)r0 * COLS + c;
    const float* pb = b + (size_t)r0 * COLS + c;

    float sa = 0.0f, sb = 0.0f;
#pragma unroll 8
    for (int r = 0; r < RPT; ++r) {          // constant trip count 32
        sa += __ldcs(pa + (size_t)r * COLS);
        sb += __ldcs(pb + (size_t)r * COLS);
    }

    // fold upper half into lower half via smem, keep atomics at 512/block
    __shared__ float sh_a[COLS];
    __shared__ float sh_b[COLS];
    if (half) {
        sh_a[c] = sa;
        sh_b[c] = sb;
    }
    __syncthreads();
    if (!half) {
        sa += sh_a[c];
        sb += sh_b[c];
        atomicAdd(&g_sa[c], sa);
        atomicAdd(&g_sb[c], sb);
    }

    // ---- last-block-done ticket ----
    __threadfence();
    __shared__ bool is_last;
    if (t == 0) {
        unsigned int tk = atomicAdd(&g_ticket, 1u);
        is_last = (tk == (unsigned)(gridDim.x - 1));
    }
    __syncthreads();
    if (!is_last) return;

    __threadfence();                         // acquire side

    float v = 0.0f;
    if (t < COLS) {
        float va = __ldcg(&g_sa[t]);
        float vb = __ldcg(&g_sb[t]);
        g_sa[t] = 0.0f;                      // reset for next graph replay
        g_sb[t] = 0.0f;
        v = va * vb;
    }

    __shared__ float red[32];
#pragma unroll
    for (int o = 16; o > 0; o >>= 1)
        v += __shfl_xor_sync(0xffffffffu, v, o);
    if ((t & 31) == 0) red[t >> 5] = v;
    __syncthreads();
    if (t < 32) {
        float w = red[t];
#pragma unroll
        for (int o = 16; o > 0; o >>= 1)
            w += __shfl_xor_sync(0xffffffffu, w, o);
        if (t == 0) {
            out[0] = w;                      // 2 * LAMBD = 1.0
            g_ticket = 0u;
        }
    }
}

extern "C" void kernel_launch(void* const* d_in, const int* in_sizes, int n_in,
                              void* d_out, int out_size) {
    const float* a = (const float*)d_in[0];
    const float* b = (const float*)d_in[1];
    float* out = (float*)d_out;

    fused_kernel<<<NBLK, TPB>>>(a, b, out);
}

// round 9
// speedup vs baseline: 1.4201x; 1.0025x over previous
#include <cuda_runtime.h>
#include <cstdint>

// loss = dot(colsum(a), colsum(b)),  a,b: [16384, 512] fp32  (2*LAMBD = 1.0)
// Bulk-async (TMA-path) streaming: producer warp issues cp.async.bulk chunks into
// a 4-stage smem ring; 512 consumer threads reduce columns from smem.
// Epilogue: global atomics -> last-block ticket -> dot + state reset.

#define ROWS   16384
#define COLS   512
#define NBLK   256
#define RPB    64                     // rows per block
#define TPB    544                    // 512 consumers + 1 producer warp
#define CHUNK  16384                  // bytes per chunk = 8 rows * 2048 B
#define CROWS  8                      // rows per chunk
#define NCHUNK 16                     // 8 a-chunks + 8 b-chunks per block
#define NSTG   4                      // ring depth
#define SMEM_DYN (NSTG * CHUNK + 64)  // buffers + mbarriers

__device__ float g_sa[COLS];
__device__ float g_sb[COLS];
__device__ unsigned int g_ticket;

__device__ __forceinline__ uint32_t smem_u32(const void* p) {
    uint32_t r;
    asm("{ .reg .u64 t; cvta.to.shared.u64 t, %1; cvt.u32.u64 %0, t; }" : "=r"(r) : "l"(p));
    return r;
}
__device__ __forceinline__ void mbar_init(uint32_t addr, uint32_t count) {
    asm volatile("mbarrier.init.shared.b64 [%0], %1;" :: "r"(addr), "r"(count) : "memory");
}
__device__ __forceinline__ void mbar_expect_tx(uint32_t addr, uint32_t bytes) {
    asm volatile("mbarrier.arrive.expect_tx.shared.b64 _, [%0], %1;" :: "r"(addr), "r"(bytes) : "memory");
}
__device__ __forceinline__ void mbar_arrive(uint32_t addr) {
    asm volatile("mbarrier.arrive.shared.b64 _, [%0];" :: "r"(addr) : "memory");
}
__device__ __forceinline__ void mbar_wait(uint32_t addr, uint32_t parity) {
    uint32_t done;
    asm volatile(
        "{\n\t.reg .pred p;\n\t"
        "mbarrier.try_wait.parity.acquire.cta.shared::cta.b64 p, [%1], %2;\n\t"
        "selp.b32 %0, 1, 0, p;\n\t}"
        : "=r"(done) : "r"(addr), "r"(parity) : "memory");
    if (!done) {
        asm volatile(
            "{\n\t.reg .pred P1;\n\t"
            "W_%=:\n\t"
            "mbarrier.try_wait.parity.acquire.cta.shared::cta.b64 P1, [%0], %1, 0x989680;\n\t"
            "@P1 bra.uni D_%=;\n\t"
            "bra.uni W_%=;\n\t"
            "D_%=:\n\t}"
            :: "r"(addr), "r"(parity) : "memory");
    }
}
__device__ __forceinline__ void bulk_copy_g2s(uint32_t dst, const void* src,
                                              uint32_t bytes, uint32_t mbar) {
    asm volatile(
        "cp.async.bulk.shared::cta.global.mbarrier::complete_tx::bytes [%0], [%1], %2, [%3];"
        :: "r"(dst), "l"(src), "r"(bytes), "r"(mbar) : "memory");
}

__global__ __launch_bounds__(TPB) void fused_kernel(const float* __restrict__ a,
                                                    const float* __restrict__ b,
                                                    float* __restrict__ out) {
    extern __shared__ __align__(128) char smem[];
    float* bufs = reinterpret_cast<float*>(smem);
    const uint32_t sbase = smem_u32(smem);
    const uint32_t bbase = sbase + NSTG * CHUNK;
    // full(s) = bbase + 16*s, empty(s) = bbase + 16*s + 8

    const int t  = threadIdx.x;
    const int r0 = blockIdx.x * RPB;

    if (t == 0) {
#pragma unroll
        for (int s = 0; s < NSTG; ++s) {
            mbar_init(bbase + 16 * s, 1);        // full: completed by tx bytes
            mbar_init(bbase + 16 * s + 8, 512);  // empty: all consumers arrive
        }
    }
    __syncthreads();

    if (t >= 512) {
        // ------- producer (single thread of last warp) -------
        if (t == 512) {
            for (int k = 0; k < NCHUNK; ++k) {
                const int s  = k & (NSTG - 1);
                const int ph = 1 ^ ((k >> 2) & 1);          // flipped phase: first waits pass
                mbar_wait(bbase + 16 * s + 8, ph);          // wait empty
                mbar_expect_tx(bbase + 16 * s, CHUNK);
                const float* src = ((k & 1) ? b : a) + (size_t)(r0 + (k >> 1) * CROWS) * COLS;
                bulk_copy_g2s(sbase + s * CHUNK, src, CHUNK, bbase + 16 * s);
            }
        }
    } else {
        // ------- consumers: thread t owns column t -------
        float sa = 0.0f, sb = 0.0f;
        for (int k = 0; k < NCHUNK; ++k) {
            const int s  = k & (NSTG - 1);
            const int ph = (k >> 2) & 1;
            mbar_wait(bbase + 16 * s, ph);                  // wait full (acquire)
            const float* bp = bufs + s * (CHUNK / 4);
            float v = 0.0f;
#pragma unroll
            for (int r = 0; r < CROWS; ++r)
                v += bp[r * COLS + t];
            if (k & 1) sb += v; else sa += v;
            mbar_arrive(bbase + 16 * s + 8);                // release empty
        }
        atomicAdd(&g_sa[t], sa);
        atomicAdd(&g_sb[t], sb);
    }

    // ---- last-block-done ticket ----
    __threadfence();
    __shared__ bool is_last;
    if (t == 0) {
        unsigned int tk = atomicAdd(&g_ticket, 1u);
        is_last = (tk == (unsigned)(gridDim.x - 1));
    }
    __syncthreads();
    if (!is_last) return;

    __threadfence();

    float v = 0.0f;
    if (t < COLS) {
        float va = __ldcg(&g_sa[t]);
        float vb = __ldcg(&g_sb[t]);
        g_sa[t] = 0.0f;                                     // reset for next replay
        g_sb[t] = 0.0f;
        v = va * vb;
    }

    __shared__ float red[17];
#pragma unroll
    for (int o = 16; o > 0; o >>= 1)
        v += __shfl_xor_sync(0xffffffffu, v, o);
    if ((t & 31) == 0) red[t >> 5] = v;
    __syncthreads();
    if (t < 32) {
        float w = (t < 17) ? red[t] : 0.0f;
#pragma unroll
        for (int o = 16; o > 0; o >>= 1)
            w += __shfl_xor_sync(0xffffffffu, w, o);
        if (t == 0) {
            out[0] = w;                                     // 2 * LAMBD = 1.0
            g_ticket = 0u;
        }
    }
}

extern "C" void kernel_launch(void* const* d_in, const int* in_sizes, int n_in,
                              void* d_out, int out_size) {
    const float* a = (const float*)d_in[0];
    const float* b = (const float*)d_in[1];
    float* out = (float*)d_out;

    static bool attr_set = false;
    if (!attr_set) {
        cudaFuncSetAttribute(fused_kernel, cudaFuncAttributeMaxDynamicSharedMemorySize, SMEM_DYN);
        attr_set = true;
    }
    fused_kernel<<<NBLK, TPB, SMEM_DYN>>>(a, b, out);
}